// round 11
// baseline (speedup 1.0000x reference)
#include <cuda_runtime.h>
#include <math.h>

#define NROWS 500000
#define NA 5
#define TT 8
#define NE 18
#define MB 4
#define EPSV 1e-8f
#define ML2 (0.02f * 0.02f)
#define BLK 128
#define RPB 256                   // rows per block (2 per thread)
#define NCLS (NE * MB * TT)       // 576

__global__ void zero_out_kernel(float* out) { out[0] = 0.0f; }

__device__ __forceinline__ float sqrt_approx(float a) {
    float r; asm("sqrt.approx.f32 %0, %1;" : "=f"(r) : "f"(a)); return r;
}
__device__ __forceinline__ float rcp_approx(float a) {
    float r; asm("rcp.approx.f32 %0, %1;" : "=f"(r) : "f"(a)); return r;
}

// one triplet for one row: LDS.64 gather + fused-angle math
__device__ __forceinline__ void tri_step(unsigned pk, unsigned avmask,
                                         const float2* __restrict__ tp,
                                         float& anum, float& aden) {
    const int ii = pk & 15;
    const int jj = (pk >> 4) & 15;
    const int kk = (pk >> 8) & 15;
    unsigned okb = (pk >> 12) & (avmask >> ii) & (avmask >> jj) & (avmask >> kk) & 1u;

    float2 j0 = tp[jj * 3 + 0], j1 = tp[jj * 3 + 1], j2 = tp[jj * 3 + 2];
    float2 i0 = tp[ii * 3 + 0], i1 = tp[ii * 3 + 1], i2 = tp[ii * 3 + 2];
    float2 k0 = tp[kk * 3 + 0], k1 = tp[kk * 3 + 1], k2 = tp[kk * 3 + 2];

    const float lo = -1.0f + 1e-6f, hi = 1.0f - 1e-6f;

    // true side (.x)
    float a1x = i0.x - j0.x, a1y = i1.x - j1.x, a1z = i2.x - j2.x;
    float a2x = k0.x - j0.x, a2y = k1.x - j1.x, a2z = k2.x - j2.x;
    float l1t = a1x * a1x + a1y * a1y + a1z * a1z;
    float l2t = a2x * a2x + a2y * a2y + a2z * a2z;
    float ddt = a1x * a2x + a1y * a2y + a1z * a2z;
    float ct = ddt * rsqrtf(fmaxf(l1t, ML2) * fmaxf(l2t, ML2));
    float sint = sqrt_approx(fmaxf(1.0f - ct * ct, 0.0f));
    ct = fminf(fmaxf(ct, lo), hi);

    // pred side (.y)
    float b1x = i0.y - j0.y, b1y = i1.y - j1.y, b1z = i2.y - j2.y;
    float b2x = k0.y - j0.y, b2y = k1.y - j1.y, b2z = k2.y - j2.y;
    float l1p = b1x * b1x + b1y * b1y + b1z * b1z;
    float l2p = b2x * b2x + b2y * b2y + b2z * b2z;
    float ddp = b1x * b2x + b1y * b2y + b1z * b2z;
    float cp = ddp * rsqrtf(fmaxf(l1p, ML2) * fmaxf(l2p, ML2));
    float sinp = sqrt_approx(fmaxf(1.0f - cp * cp, 0.0f));
    cp = fminf(fmaxf(cp, lo), hi);

    bool ok = okb && (l1t > ML2) && (l2t > ML2) && (l1p > ML2) && (l2p > ML2);
    float dc = cp - ct;
    float ds = sinp - sint;
    if (ok) { anum += dc * dc + ds * ds; aden += 1.0f; }
}

// atom MSE + class lookup prologue for one row
__device__ __forceinline__ void row_prologue(const float2* __restrict__ tp, unsigned mb,
                                             float gate, float bd,
                                             float& atom, unsigned& avmask, int& base) {
    float num = 0.0f;
    avmask = 0;
#pragma unroll
    for (int a = 0; a < NA; a++) {
        float2 q0 = tp[3 * a + 0];
        float2 q1 = tp[3 * a + 1];
        float2 q2 = tp[3 * a + 2];
        float d0 = q0.x - q0.y, d1 = q1.x - q1.y, d2 = q2.x - q2.y;
        unsigned g = (mb >> (3 * a)) & 7u;
        num += ((g & 1u) ? d0 * d0 : 0.0f)
             + ((g & 2u) ? d1 * d1 : 0.0f)
             + ((g & 4u) ? d2 * d2 : 0.0f);
        avmask |= (g ? 1u : 0u) << a;
    }
    atom = num * rcp_approx((float)__popc(avmask) + EPSV);

    if (!isfinite(gate)) gate = 0.0f;
    int rid = (int)rintf(gate) - 1;
    rid = min(max(rid, 0), NE - 1);
    if (!isfinite(bd)) bd = 0.0f;
    int bid = min(max((int)rintf(bd), 0), MB - 1);
    base = (rid * MB + bid) * TT;
}

__global__ void __launch_bounds__(BLK, 6) loss_kernel(
    const float* __restrict__ x,
    const float* __restrict__ yt,
    const float* __restrict__ yp,
    const float* __restrict__ mk,
    const int* __restrict__ trip,
    const int* __restrict__ tvalid,
    float* __restrict__ out)
{
    __shared__ __align__(16) unsigned s_pk[NCLS];     // 2.3 KB
    __shared__ __align__(16) float2  s_tp[RPB * 15];  // interleaved {t,p}: 30 KB
    __shared__ float warpsum[BLK / 32];

    const int tid  = threadIdx.x;
    const int row0 = blockIdx.x * RPB;
    const int cnt  = min(RPB, NROWS - row0);
    const int rowA = row0 + tid;
    const int rowB = row0 + BLK + tid;
    const bool liveA = (rowA < NROWS);
    const bool liveB = (rowB < NROWS);

    // early per-row loads (LDG, overlaps staging): mask bits + gate/bead
    unsigned mbA = 0, mbB = 0;
    float gateA = 0.0f, bdA = 0.0f, gateB = 0.0f, bdB = 0.0f;
    if (liveA) {
        const float* mrow = mk + (size_t)rowA * 15;
#pragma unroll
        for (int e = 0; e < 15; e++) mbA |= (mrow[e] > 0.0f ? 1u : 0u) << e;
        const float2 xg = *(const float2*)(x + (size_t)rowA * 38 + 36);
        bdA = xg.x; gateA = xg.y;
    }
    if (liveB) {
        const float* mrow = mk + (size_t)rowB * 15;
#pragma unroll
        for (int e = 0; e < 15; e++) mbB |= (mrow[e] > 0.0f ? 1u : 0u) << e;
        const float2 xg = *(const float2*)(x + (size_t)rowB * 38 + 36);
        bdB = xg.x; gateB = xg.y;
    }

    // -------- pack tables --------
    for (int e = tid; e < NCLS; e += BLK) {
        const int i0 = trip[3 * e + 0];
        const int i1 = trip[3 * e + 1];
        const int i2 = trip[3 * e + 2];
        const int v  = tvalid[e];
        const unsigned ok = (i0 >= 0 && i1 >= 0 && i2 >= 0 && v > 0) ? 1u : 0u;
        const unsigned ii = (unsigned)max(i0, 0);
        const unsigned jj = (unsigned)max(i1, 0);
        const unsigned kk = (unsigned)max(i2, 0);
        s_pk[e] = ii | (jj << 4) | (kk << 8) | (ok << 12);
    }

    // -------- coalesced staging of 256 rows, {t,p} interleaved --------
    if (cnt == RPB) {
        const float2* gt2 = (const float2*)(yt + (size_t)row0 * 15);
        const float2* gp2 = (const float2*)(yp + (size_t)row0 * 15);
        float4* d4 = (float4*)s_tp;
#pragma unroll
        for (int k = 0; k < 15; k++) {
            int i = tid + k * BLK;     // i < 1920 exactly covers 15*128
            float2 a = gt2[i];
            float2 b = gp2[i];
            d4[i] = make_float4(a.x, b.x, a.y, b.y);  // s_tp[2i], s_tp[2i+1]
        }
    } else {
        const int tot = cnt * 15;
        const float* gt = yt + (size_t)row0 * 15;
        const float* gp = yp + (size_t)row0 * 15;
        for (int i = tid; i < tot; i += BLK)
            s_tp[i] = make_float2(gt[i], gp[i]);
    }
    __syncthreads();

    const float2* tpA = s_tp + tid * 15;
    const float2* tpB = s_tp + (BLK + tid) * 15;

    // prologues (dead rows: mb=0 -> atom=0, avmask=0 -> all triplets invalid -> ang=0)
    float atomA, atomB;
    unsigned avA, avB;
    int baseA, baseB;
    row_prologue(tpA, mbA, gateA, bdA, atomA, avA, baseA);
    row_prologue(tpB, mbB, gateB, bdB, atomB, avB, baseB);

    const uint4* pkpA = (const uint4*)(s_pk + baseA);
    const uint4* pkpB = (const uint4*)(s_pk + baseB);

    float anumA = 0.0f, adenA = 0.0f, anumB = 0.0f, adenB = 0.0f;

#pragma unroll
    for (int h = 0; h < 2; h++) {
        const uint4 a4 = pkpA[h];
        const uint4 b4 = pkpB[h];
        const unsigned wa[4] = { a4.x, a4.y, a4.z, a4.w };
        const unsigned wb[4] = { b4.x, b4.y, b4.z, b4.w };
#pragma unroll
        for (int e = 0; e < 4; e++) {
            tri_step(wa[e], avA, tpA, anumA, adenA);   // two independent chains
            tri_step(wb[e], avB, tpB, anumB, adenB);   // interleaved by scheduler
        }
    }

    float accA = liveA ? (atomA + anumA * rcp_approx(adenA + EPSV)) : 0.0f;
    float accB = liveB ? (atomB + anumB * rcp_approx(adenB + EPSV)) : 0.0f;
    float acc = accA + accB;

    // ---------------- block reduction ----------------
#pragma unroll
    for (int off = 16; off > 0; off >>= 1)
        acc += __shfl_down_sync(0xffffffffu, acc, off);

    if ((tid & 31) == 0) warpsum[tid >> 5] = acc;
    __syncthreads();
    if (tid == 0) {
        float s = 0.0f;
#pragma unroll
        for (int w = 0; w < BLK / 32; w++) s += warpsum[w];
        atomicAdd(out, s * (1.0f / (float)NROWS));
    }
}

extern "C" void kernel_launch(void* const* d_in, const int* in_sizes, int n_in,
                              void* d_out, int out_size)
{
    const float* x      = (const float*)d_in[0];
    const float* yt     = (const float*)d_in[1];
    const float* yp     = (const float*)d_in[2];
    const float* mk     = (const float*)d_in[3];
    const int*   trip   = (const int*)d_in[4];
    const int*   tvalid = (const int*)d_in[5];
    float* out = (float*)d_out;

    zero_out_kernel<<<1, 1>>>(out);
    const int grid = (NROWS + RPB - 1) / RPB;   // 1954
    loss_kernel<<<grid, BLK>>>(x, yt, yp, mk, trip, tvalid, out);
}

// round 12
// speedup vs baseline: 1.0861x; 1.0861x over previous
#include <cuda_runtime.h>
#include <math.h>

#define NROWS 500000
#define NA 5
#define TT 8
#define NE 18
#define MB 4
#define EPSV 1e-8f
#define ML2 (0.02f * 0.02f)
#define BLK 128
#define NCLS (NE * MB * TT)   // 576

__global__ void zero_out_kernel(float* out) { out[0] = 0.0f; }

__device__ __forceinline__ float sqrt_approx(float a) {
    float r; asm("sqrt.approx.f32 %0, %1;" : "=f"(r) : "f"(a)); return r;
}
__device__ __forceinline__ float rcp_approx(float a) {
    float r; asm("rcp.approx.f32 %0, %1;" : "=f"(r) : "f"(a)); return r;
}

__global__ void __launch_bounds__(BLK, 10) loss_kernel(
    const float* __restrict__ x,
    const float* __restrict__ yt,
    const float* __restrict__ yp,
    const float* __restrict__ mk,
    const int* __restrict__ trip,
    const int* __restrict__ tvalid,
    float* __restrict__ out)
{
    __shared__ __align__(16) unsigned s_pk[NCLS];    // 2.3 KB
    __shared__ __align__(16) float2  s_tp[BLK * 15]; // interleaved {t,p}: 15 KB
    __shared__ unsigned s_mb[BLK];                   // per-row 15-bit mask: 512 B
    __shared__ float warpsum[BLK / 32];

    const int tid  = threadIdx.x;
    const int row0 = blockIdx.x * BLK;
    const int cnt  = min(BLK, NROWS - row0);
    const bool live = (tid < cnt);
    const int row  = row0 + tid;

    // early gate/bead load (one strided LDG.64/thread)
    float gate = 0.0f, bd = 0.0f;
    if (live) {
        const float2 xg = *(const float2*)(x + (size_t)row * 38 + 36);
        bd = xg.x; gate = xg.y;
    }

    s_mb[tid] = 0u;

    // -------- pack tables --------
    for (int e = tid; e < NCLS; e += BLK) {
        const int i0 = trip[3 * e + 0];
        const int i1 = trip[3 * e + 1];
        const int i2 = trip[3 * e + 2];
        const int v  = tvalid[e];
        const unsigned ok = (i0 >= 0 && i1 >= 0 && i2 >= 0 && v > 0) ? 1u : 0u;
        const unsigned ii = (unsigned)max(i0, 0);
        const unsigned jj = (unsigned)max(i1, 0);
        const unsigned kk = (unsigned)max(i2, 0);
        s_pk[e] = ii | (jj << 4) | (kk << 8) | (ok << 12);
    }
    __syncthreads();   // s_mb init visible before atomicOr

    // -------- coalesced staging: {t,p} interleaved + mask bits via atomicOr --------
    if (cnt == BLK) {
        const float2* gt2 = (const float2*)(yt + (size_t)row0 * 15);
        const float2* gp2 = (const float2*)(yp + (size_t)row0 * 15);
        const float4* gm4 = (const float4*)(mk + (size_t)row0 * 15);
        float4* d4 = (float4*)s_tp;
#pragma unroll
        for (int k = 0; k < 8; k++) {
            int i = tid + k * BLK;
            if (i < 960) {
                float2 a = gt2[i];
                float2 b = gp2[i];
                d4[i] = make_float4(a.x, b.x, a.y, b.y);  // s_tp[2i], s_tp[2i+1]
            }
            if (i < 480) {
                float4 mv = gm4[i];           // coalesced LDG.128
                float vals[4] = { mv.x, mv.y, mv.z, mv.w };
                const int g0 = 4 * i;
                const int r0 = g0 / 15;
                unsigned b0 = 0, b1 = 0;
#pragma unroll
                for (int e = 0; e < 4; e++) {
                    int g = g0 + e;
                    int r = g / 15, c = g - r * 15;
                    unsigned b = (vals[e] > 0.0f) ? (1u << c) : 0u;
                    if (r == r0) b0 |= b; else b1 |= b;
                }
                if (b0) atomicOr(&s_mb[r0], b0);
                if (b1) atomicOr(&s_mb[r0 + 1], b1);
            }
        }
    } else {
        const int tot = cnt * 15;
        const float* gt = yt + (size_t)row0 * 15;
        const float* gp = yp + (size_t)row0 * 15;
        const float* gm = mk + (size_t)row0 * 15;
        for (int i = tid; i < tot; i += BLK) {
            s_tp[i] = make_float2(gt[i], gp[i]);
            float mv = gm[i];
            if (mv > 0.0f) atomicOr(&s_mb[i / 15], 1u << (i % 15));
        }
    }
    __syncthreads();

    float acc = 0.0f;

    if (live) {
        const float2* tp = s_tp + tid * 15;  // 120B lane stride: conflict-free per phase
        const unsigned mb = s_mb[tid];       // one LDS.32

        // ---------------- atom MSE ----------------
        unsigned avmask = 0;
        float num = 0.0f;
#pragma unroll
        for (int a = 0; a < NA; a++) {
            float2 q0 = tp[3 * a + 0];
            float2 q1 = tp[3 * a + 1];
            float2 q2 = tp[3 * a + 2];
            float d0 = q0.x - q0.y, d1 = q1.x - q1.y, d2 = q2.x - q2.y;
            unsigned g = (mb >> (3 * a)) & 7u;
            num += ((g & 1u) ? d0 * d0 : 0.0f)
                 + ((g & 2u) ? d1 * d1 : 0.0f)
                 + ((g & 4u) ? d2 * d2 : 0.0f);
            avmask |= (g ? 1u : 0u) << a;
        }
        float atom = num * rcp_approx((float)__popc(avmask) + EPSV);

        // ---------------- angle loss ----------------
        if (!isfinite(gate)) gate = 0.0f;
        int rid = (int)rintf(gate) - 1;
        rid = min(max(rid, 0), NE - 1);
        if (!isfinite(bd)) bd = 0.0f;
        int bid = min(max((int)rintf(bd), 0), MB - 1);

        const int base = (rid * MB + bid) * TT;      // multiple of 8 -> 32B aligned
        const uint4* pkp = (const uint4*)(s_pk + base);

        const float lo = -1.0f + 1e-6f, hi = 1.0f - 1e-6f;
        float anum = 0.0f, aden = 0.0f;

#pragma unroll
        for (int h = 0; h < 2; h++) {
            const uint4 pk4 = pkp[h];
            const unsigned pkw[4] = { pk4.x, pk4.y, pk4.z, pk4.w };
#pragma unroll
            for (int e = 0; e < 4; e++) {
                const unsigned pk = pkw[e];
                const int ii = pk & 15;
                const int jj = (pk >> 4) & 15;
                const int kk = (pk >> 8) & 15;
                unsigned okb = (pk >> 12) & (avmask >> ii) & (avmask >> jj) & (avmask >> kk) & 1u;

                // one LDS.64 per component serves BOTH true (.x) and pred (.y)
                float2 j0 = tp[jj * 3 + 0], j1 = tp[jj * 3 + 1], j2 = tp[jj * 3 + 2];
                float2 i0 = tp[ii * 3 + 0], i1 = tp[ii * 3 + 1], i2 = tp[ii * 3 + 2];
                float2 k0 = tp[kk * 3 + 0], k1 = tp[kk * 3 + 1], k2 = tp[kk * 3 + 2];

                // ---- true side (.x) ----
                float a1x = i0.x - j0.x, a1y = i1.x - j1.x, a1z = i2.x - j2.x;
                float a2x = k0.x - j0.x, a2y = k1.x - j1.x, a2z = k2.x - j2.x;
                float l1t = a1x * a1x + a1y * a1y + a1z * a1z;
                float l2t = a2x * a2x + a2y * a2y + a2z * a2z;
                float ddt = a1x * a2x + a1y * a2y + a1z * a2z;
                float ct = ddt * rsqrtf(fmaxf(l1t, ML2) * fmaxf(l2t, ML2));
                float sint = sqrt_approx(fmaxf(1.0f - ct * ct, 0.0f));
                ct = fminf(fmaxf(ct, lo), hi);

                // ---- pred side (.y) ----
                float b1x = i0.y - j0.y, b1y = i1.y - j1.y, b1z = i2.y - j2.y;
                float b2x = k0.y - j0.y, b2y = k1.y - j1.y, b2z = k2.y - j2.y;
                float l1p = b1x * b1x + b1y * b1y + b1z * b1z;
                float l2p = b2x * b2x + b2y * b2y + b2z * b2z;
                float ddp = b1x * b2x + b1y * b2y + b1z * b2z;
                float cp = ddp * rsqrtf(fmaxf(l1p, ML2) * fmaxf(l2p, ML2));
                float sinp = sqrt_approx(fmaxf(1.0f - cp * cp, 0.0f));
                cp = fminf(fmaxf(cp, lo), hi);

                bool ok = okb && (l1t > ML2) && (l2t > ML2) && (l1p > ML2) && (l2p > ML2);

                float dc = cp - ct;
                float ds = sinp - sint;
                if (ok) { anum += dc * dc + ds * ds; aden += 1.0f; }
            }
        }
        float ang = anum * rcp_approx(aden + EPSV);

        acc = atom + ang;
    }

    // ---------------- block reduction ----------------
#pragma unroll
    for (int off = 16; off > 0; off >>= 1)
        acc += __shfl_down_sync(0xffffffffu, acc, off);

    if ((tid & 31) == 0) warpsum[tid >> 5] = acc;
    __syncthreads();
    if (tid == 0) {
        float s = 0.0f;
#pragma unroll
        for (int w = 0; w < BLK / 32; w++) s += warpsum[w];
        atomicAdd(out, s * (1.0f / (float)NROWS));
    }
}

extern "C" void kernel_launch(void* const* d_in, const int* in_sizes, int n_in,
                              void* d_out, int out_size)
{
    const float* x      = (const float*)d_in[0];
    const float* yt     = (const float*)d_in[1];
    const float* yp     = (const float*)d_in[2];
    const float* mk     = (const float*)d_in[3];
    const int*   trip   = (const int*)d_in[4];
    const int*   tvalid = (const int*)d_in[5];
    float* out = (float*)d_out;

    zero_out_kernel<<<1, 1>>>(out);
    const int grid = (NROWS + BLK - 1) / BLK;
    loss_kernel<<<grid, BLK>>>(x, yt, yp, mk, trip, tvalid, out);
}